// round 2
// baseline (speedup 1.0000x reference)
#include <cuda_runtime.h>
#include <cstdint>

#define B_  4
#define C_  256
#define H_  96
#define W_  128
#define P_  9

#define TX  32           // x pixels per block
#define TY  4            // y pixels per block
#define PT  8            // x pixels per thread
#define XG  (TX / PT)    // 4 x-groups
#define THREADS (XG * P_ * TY)   // 144
#define CC  8            // channels per stage
#define NSTAGE (C_ / CC) // 32
#define HALO_W  40       // useful halo width (floats)
#define HALO_WP 44       // padded row stride (floats) -> 176B, conflict-free
#define HALO_H (TY + 8)  // 12

#define S1_BUF_FLOATS (CC * TY * TX)            // 1024
#define S2_BUF_FLOATS (CC * HALO_H * HALO_WP)   // 4224
#define S1_BUF_BYTES  (S1_BUF_FLOATS * 4)       // 4096
#define S2_BUF_BYTES  (S2_BUF_FLOATS * 4)       // 16896

// float4 loads per stage
#define N_LD1 (CC * TY * (TX / 4))              // 256
#define N_LD2 (CC * HALO_H * (HALO_W / 4))      // 960
#define N_LD  (N_LD1 + N_LD2)                   // 1216
#define LD_PER_THREAD 9                         // ceil(1216/144)

typedef unsigned long long u64;

__device__ __forceinline__ void cp_async16(uint32_t dst, const void* src, int srcsize) {
    asm volatile("cp.async.cg.shared.global [%0], [%1], 16, %2;\n"
                 :: "r"(dst), "l"(src), "r"(srcsize));
}
__device__ __forceinline__ void cp_commit() {
    asm volatile("cp.async.commit_group;\n" ::: "memory");
}
template <int N>
__device__ __forceinline__ void cp_wait() {
    asm volatile("cp.async.wait_group %0;\n" :: "n"(N) : "memory");
}

// pack two fp32 into one 64-bit reg (register pair)
__device__ __forceinline__ u64 pk2(float lo, float hi) {
    u64 r;
    asm("mov.b64 %0, {%1, %2};" : "=l"(r) : "f"(lo), "f"(hi));
    return r;
}
// packed dual-FMA: d.lo += a.lo*b.lo ; d.hi += a.hi*b.hi  (SASS FFMA2)
__device__ __forceinline__ void fma2(u64& d, u64 a, u64 b) {
    asm("fma.rn.f32x2 %0, %1, %2, %0;" : "+l"(d) : "l"(a), "l"(b));
}
__device__ __forceinline__ void unpk2(float& lo, float& hi, u64 v) {
    asm("mov.b64 {%0, %1}, %2;" : "=f"(lo), "=f"(hi) : "l"(v));
}

__global__ void __launch_bounds__(THREADS, 3)
corr_kernel(const float* __restrict__ in1,
            const float* __restrict__ in2,
            float* __restrict__ out)
{
    __shared__ __align__(16) float s1[2][CC][TY][TX];            // in1 tile
    __shared__ __align__(16) float s2[2][CC][HALO_H][HALO_WP];   // in2 halo (padded rows)

    const int tid = threadIdx.x;
    const int b   = blockIdx.z;
    const int y0  = blockIdx.y * TY;
    const int x0  = blockIdx.x * TX;

    const float* g1 = in1 + (size_t)b * C_ * H_ * W_;
    const float* g2 = in2 + (size_t)b * C_ * H_ * W_;

    const uint32_t s1base = (uint32_t)__cvta_generic_to_shared(&s1[0][0][0][0]);
    const uint32_t s2base = (uint32_t)__cvta_generic_to_shared(&s2[0][0][0][0]);

    // ---- per-thread cp.async load descriptors (stage 0, buffer 0) ----
    uint32_t     l_soff[LD_PER_THREAD];
    const float* l_gptr[LD_PER_THREAD];
    int          l_sz  [LD_PER_THREAD];
    uint32_t     l_bstr[LD_PER_THREAD];

    #pragma unroll
    for (int k = 0; k < LD_PER_THREAD; k++) {
        int idx = tid + k * THREADS;
        if (idx < N_LD1) {
            // in1 tile: 32 float4 per channel (4 rows x 8 chunks)
            int cc = idx >> 5;
            int r  = idx & 31;
            int yy = r >> 3;
            int j  = r & 7;
            l_soff[k] = s1base + (uint32_t)(((cc * TY + yy) * TX + j * 4) * 4);
            l_gptr[k] = g1 + ((size_t)cc * H_ + (y0 + yy)) * W_ + x0 + 4 * j;
            l_sz[k]   = 16;
            l_bstr[k] = S1_BUF_BYTES;
        } else if (idx < N_LD) {
            // in2 halo: 120 float4 per channel (12 rows x 10 chunks), padded rows
            int id2 = idx - N_LD1;
            int cc  = id2 / 120;
            int r   = id2 - cc * 120;
            int ry  = r / 10;
            int j   = r - ry * 10;
            int gy  = y0 + ry - 4;
            int gx  = x0 + 4 * j - 4;
            bool inb = (gy >= 0) && (gy < H_) && (gx >= 0) && (gx <= W_ - 4);
            l_soff[k] = s2base + (uint32_t)(((cc * HALO_H + ry) * HALO_WP + j * 4) * 4);
            l_gptr[k] = inb ? (g2 + ((size_t)cc * H_ + gy) * W_ + gx) : g2;
            l_sz[k]   = inb ? 16 : 0;   // src-size 0 => zero-fill
            l_bstr[k] = S2_BUF_BYTES;
        } else {
            l_sz[k]   = -1;
            l_soff[k] = 0;
            l_gptr[k] = g1;
            l_bstr[k] = 0;
        }
    }

    // ---- compute-role decomposition: tid = (yy*9 + dy)*4 + g ----
    const int g   = tid & 3;          // x-group (0..3), 8 px each
    const int dy  = (tid >> 2) % 9;   // shift row (0..8)
    const int yy  = tid / 36;         // block-local output row (0..3)

    // packed accumulators: acc2[t2][d] holds outputs x = 8g+2*t2, 8g+2*t2+1
    u64 acc2[PT / 2][P_];
    #pragma unroll
    for (int t = 0; t < PT / 2; t++)
        #pragma unroll
        for (int d = 0; d < P_; d++)
            acc2[t][d] = 0ull;

    const float* w_base = &s2[0][0][yy + dy][8 * g];  // 16-float window start
    const float* a_base = &s1[0][0][yy][8 * g];       // 8-float in1 start

    // ---- prologue: issue stage 0 ----
    #pragma unroll
    for (int k = 0; k < LD_PER_THREAD; k++)
        if (l_sz[k] >= 0)
            cp_async16(l_soff[k], l_gptr[k], l_sz[k]);
    cp_commit();

    for (int st = 0; st < NSTAGE; st++) {
        cp_wait<0>();        // stage st landed (only group in flight)
        __syncthreads();     // visible to all warps; prev reads of next buf done

        if (st + 1 < NSTAGE) {
            const int    buf  = (st + 1) & 1;
            const size_t goff = (size_t)(st + 1) * CC * H_ * W_;
            #pragma unroll
            for (int k = 0; k < LD_PER_THREAD; k++)
                if (l_sz[k] >= 0)
                    cp_async16(l_soff[k] + buf * l_bstr[k], l_gptr[k] + goff, l_sz[k]);
            cp_commit();
        }

        const int buf = st & 1;
        const float* wp = w_base + buf * S2_BUF_FLOATS;
        const float* ap = a_base + buf * S1_BUF_FLOATS;

        #pragma unroll 1
        for (int cc = 0; cc < CC; cc++) {
            const float4* wp4 = reinterpret_cast<const float4*>(wp);
            float4 w0 = wp4[0], w1 = wp4[1], w2 = wp4[2], w3 = wp4[3];
            const float4* ap4 = reinterpret_cast<const float4*>(ap);
            float4 a0 = ap4[0], a1 = ap4[1];

            u64 av0 = pk2(a0.x, a0.y);
            u64 av1 = pk2(a0.z, a0.w);
            u64 av2 = pk2(a1.x, a1.y);
            u64 av3 = pk2(a1.z, a1.w);

            float wf[16];
            wf[0]  = w0.x; wf[1]  = w0.y; wf[2]  = w0.z; wf[3]  = w0.w;
            wf[4]  = w1.x; wf[5]  = w1.y; wf[6]  = w1.z; wf[7]  = w1.w;
            wf[8]  = w2.x; wf[9]  = w2.y; wf[10] = w2.z; wf[11] = w2.w;
            wf[12] = w3.x; wf[13] = w3.y; wf[14] = w3.z; wf[15] = w3.w;

            u64 wpair[15];
            #pragma unroll
            for (int k = 0; k < 15; k++)
                wpair[k] = pk2(wf[k], wf[k + 1]);

            #pragma unroll
            for (int d = 0; d < P_; d++) {
                fma2(acc2[0][d], av0, wpair[d]);
                fma2(acc2[1][d], av1, wpair[d + 2]);
                fma2(acc2[2][d], av2, wpair[d + 4]);
                fma2(acc2[3][d], av3, wpair[d + 6]);
            }

            wp += HALO_H * HALO_WP;
            ap += TY * TX;
        }
        __syncthreads();
    }

    // ---- write output: out[b][dy][d][y0+yy][x0+8g .. +7] ----
    {
        const size_t hw = (size_t)H_ * W_;
        float* obase = out + (((size_t)b * P_ + dy) * P_) * hw
                     + (size_t)(y0 + yy) * W_ + x0 + 8 * g;
        #pragma unroll
        for (int d = 0; d < P_; d++) {
            float4 v0, v1;
            unpk2(v0.x, v0.y, acc2[0][d]);
            unpk2(v0.z, v0.w, acc2[1][d]);
            unpk2(v1.x, v1.y, acc2[2][d]);
            unpk2(v1.z, v1.w, acc2[3][d]);
            *reinterpret_cast<float4*>(obase + (size_t)d * hw)     = v0;
            *reinterpret_cast<float4*>(obase + (size_t)d * hw + 4) = v1;
        }
    }
}

extern "C" void kernel_launch(void* const* d_in, const int* in_sizes, int n_in,
                              void* d_out, int out_size) {
    const float* in1 = (const float*)d_in[0];
    const float* in2 = (const float*)d_in[1];
    float* out = (float*)d_out;

    dim3 grid(W_ / TX, H_ / TY, B_);   // (4, 24, 4) = 384 blocks
    dim3 block(THREADS);               // 144
    corr_kernel<<<grid, block>>>(in1, in2, out);
}

// round 3
// speedup vs baseline: 1.1188x; 1.1188x over previous
#include <cuda_runtime.h>
#include <cstdint>

#define B_  4
#define C_  256
#define H_  96
#define W_  128
#define P_  9

#define TX  32           // x pixels per block
#define TY  4            // y pixels per block
#define PT  4            // x pixels per thread
#define XG  (TX / PT)    // 8
#define THREADS 288      // XG * 9 * TY
#define CC  8            // channels per stage
#define NSTAGE (C_ / CC) // 32
#define HALO_WP 44       // padded halo row stride (floats)
#define HALO_H  12

#define S1F (CC * TY * TX)            // 1024 floats
#define S2F (CC * HALO_H * HALO_WP)   // 4224 floats
#define STAGEF (S1F + S2F)            // 5248 floats
#define STAGEB (STAGEF * 4)           // 20992 bytes
#define GSTAGEB (CC * H_ * W_ * 4)    // 393216 bytes per stage in gmem

#define N_LD1 256                     // in1 float4 chunks per stage
#define N_LD2 960                     // in2 float4 chunks per stage
#define N_LD  1216

#define FLAG_OOB (1u << 26)
#define FLAG_IN2 (1u << 27)

typedef unsigned long long u64;

__device__ __forceinline__ void cp_async16(uint32_t dst, const void* src, int srcsize) {
    asm volatile("cp.async.cg.shared.global [%0], [%1], 16, %2;\n"
                 :: "r"(dst), "l"(src), "r"(srcsize));
}
__device__ __forceinline__ void cp_commit() {
    asm volatile("cp.async.commit_group;\n" ::: "memory");
}
template <int N>
__device__ __forceinline__ void cp_wait() {
    asm volatile("cp.async.wait_group %0;\n" :: "n"(N) : "memory");
}

__device__ __forceinline__ u64 pk2(float lo, float hi) {
    u64 r;
    asm("mov.b64 %0, {%1, %2};" : "=l"(r) : "f"(lo), "f"(hi));
    return r;
}
// packed dual-FMA on fma pipe (FFMA2): d.lo += a.lo*b.lo ; d.hi += a.hi*b.hi
__device__ __forceinline__ void fma2(u64& d, u64 a, u64 b) {
    asm("fma.rn.f32x2 %0, %1, %2, %0;" : "+l"(d) : "l"(a), "l"(b));
}
__device__ __forceinline__ void unpk2(float& lo, float& hi, u64 v) {
    asm("mov.b64 {%0, %1}, %2;" : "=f"(lo), "=f"(hi) : "l"(v));
}

__global__ void __launch_bounds__(THREADS, 3)
corr_kernel(const float* __restrict__ in1,
            const float* __restrict__ in2,
            float* __restrict__ out)
{
    __shared__ __align__(16) float    sbuf[2][STAGEF];  // [buf][ s1 tile | s2 halo ]
    __shared__             uint32_t   desc[N_LD];       // packed load descriptors

    const int tid = threadIdx.x;
    const int b   = blockIdx.z;
    const int y0  = blockIdx.y * TY;
    const int x0  = blockIdx.x * TX;

    const char* g1 = (const char*)(in1 + (size_t)b * C_ * H_ * W_);
    const char* g2 = (const char*)(in2 + (size_t)b * C_ * H_ * W_);

    const uint32_t sbase = (uint32_t)__cvta_generic_to_shared(&sbuf[0][0]);

    // ---- build packed descriptor table (once per block) ----
    for (int i = tid; i < N_LD; i += THREADS) {
        uint32_t soff, goff, flags = 0;
        if (i < N_LD1) {
            // in1 tile: 32 chunks per channel (4 rows x 8 float4)
            int cc = i >> 5;
            int r  = i & 31;
            int ry = r >> 3;
            int j  = r & 7;
            soff = (uint32_t)(((cc * TY + ry) * TX + 4 * j) * 4);
            goff = (uint32_t)(((cc * H_ + (y0 + ry)) * W_ + x0 + 4 * j) * 4);
        } else {
            // in2 halo: 120 chunks per channel (12 rows x 10 float4), padded rows
            int t  = i - N_LD1;
            int cc = t / 120;
            int r  = t - cc * 120;
            int ry = r / 10;
            int j  = r - ry * 10;
            soff = (uint32_t)(S1F * 4 + ((cc * HALO_H + ry) * HALO_WP + 4 * j) * 4);
            int gy = y0 + ry - 4;
            int gx = x0 + 4 * j - 4;
            bool oob = (gy < 0) || (gy >= H_) || (gx < 0) || (gx > W_ - 4);
            goff = oob ? 0u : (uint32_t)(((cc * H_ + gy) * W_ + gx) * 4);
            flags = FLAG_IN2 | (oob ? FLAG_OOB : 0u);
        }
        desc[i] = (soff >> 4) | ((goff >> 4) << 11) | flags;
    }

    // ---- compute-role decomposition: tid = (yy*9 + dy)*8 + g ----
    const int g   = tid & 7;          // x-group (0..7), 4 px each
    const int dy  = (tid >> 3) % 9;   // shift row (0..8)
    const int yy  = tid / 72;         // block-local output row (0..3)

    u64 acc2[PT / 2][P_];             // (x pair) x (dx) packed accumulators
    #pragma unroll
    for (int t = 0; t < PT / 2; t++)
        #pragma unroll
        for (int d = 0; d < P_; d++)
            acc2[t][d] = 0ull;

    const int w_off = S1F + (yy + dy) * HALO_WP + 4 * g;  // window base (buf 0, cc 0)
    const int a_off = yy * TX + 4 * g;                    // in1 base

    __syncthreads();   // desc table ready

    // ---- prologue: issue stage 0 ----
    for (int i = tid; i < N_LD; i += THREADS) {
        uint32_t d = desc[i];
        uint32_t soff = (d & 0x7FFu) << 4;
        const char* src = ((d & FLAG_IN2) ? g2 : g1) + (((d >> 11) & 0x7FFFu) << 4);
        cp_async16(sbase + soff, src, (d & FLAG_OOB) ? 0 : 16);
    }
    cp_commit();

    for (int st = 0; st < NSTAGE; st++) {
        cp_wait<0>();
        __syncthreads();   // stage st visible to all; prev reads of other buf done

        if (st + 1 < NSTAGE) {
            const uint32_t buf_add = (uint32_t)((st + 1) & 1) * STAGEB;
            const size_t   gadd    = (size_t)(st + 1) * GSTAGEB;
            for (int i = tid; i < N_LD; i += THREADS) {
                uint32_t d = desc[i];
                uint32_t soff = (d & 0x7FFu) << 4;
                const char* src = ((d & FLAG_IN2) ? g2 : g1)
                                + ((((d >> 11) & 0x7FFFu) << 4) + gadd);
                cp_async16(sbase + soff + buf_add, src, (d & FLAG_OOB) ? 0 : 16);
            }
            cp_commit();
        }

        const int base = (st & 1) * STAGEF;
        const float* wp = &sbuf[0][base + w_off];
        const float* ap = &sbuf[0][base + a_off];

        #pragma unroll 2
        for (int cc = 0; cc < CC; cc++) {
            const float4* wp4 = reinterpret_cast<const float4*>(wp);
            float4 w0 = wp4[0], w1 = wp4[1], w2 = wp4[2];
            float4 a  = *reinterpret_cast<const float4*>(ap);

            u64 av0 = pk2(a.x, a.y);
            u64 av1 = pk2(a.z, a.w);

            float wf[12];
            wf[0] = w0.x; wf[1]  = w0.y; wf[2]  = w0.z; wf[3]  = w0.w;
            wf[4] = w1.x; wf[5]  = w1.y; wf[6]  = w1.z; wf[7]  = w1.w;
            wf[8] = w2.x; wf[9]  = w2.y; wf[10] = w2.z; wf[11] = w2.w;

            u64 wq[11];
            #pragma unroll
            for (int k = 0; k < 11; k++)
                wq[k] = pk2(wf[k], wf[k + 1]);

            #pragma unroll
            for (int d = 0; d < P_; d++) {
                fma2(acc2[0][d], av0, wq[d]);
                fma2(acc2[1][d], av1, wq[d + 2]);
            }

            wp += HALO_H * HALO_WP;
            ap += TY * TX;
        }
        __syncthreads();
    }

    // ---- write output: out[b][dy][d][y0+yy][x0+4g .. +3] ----
    {
        const size_t hw = (size_t)H_ * W_;
        float* obase = out + (((size_t)b * P_ + dy) * P_) * hw
                     + (size_t)(y0 + yy) * W_ + x0 + 4 * g;
        #pragma unroll
        for (int d = 0; d < P_; d++) {
            float4 v;
            unpk2(v.x, v.y, acc2[0][d]);
            unpk2(v.z, v.w, acc2[1][d]);
            *reinterpret_cast<float4*>(obase + (size_t)d * hw) = v;
        }
    }
}

extern "C" void kernel_launch(void* const* d_in, const int* in_sizes, int n_in,
                              void* d_out, int out_size) {
    const float* in1 = (const float*)d_in[0];
    const float* in2 = (const float*)d_in[1];
    float* out = (float*)d_out;

    dim3 grid(W_ / TX, H_ / TY, B_);   // (4, 24, 4) = 384 blocks
    dim3 block(THREADS);               // 288
    corr_kernel<<<grid, block>>>(in1, in2, out);
}